// round 1
// baseline (speedup 1.0000x reference)
#include <cuda_runtime.h>
#include <math.h>

// Problem shape (fixed by the reference)
#define B_   32
#define C_   512
#define MID_ 32
#define HW_  3136          // 56*56
#define HW4_ 784           // HW_/4
#define ROWS_ (B_ * C_)    // 16384

// Scratch (allocation-free rule: __device__ globals)
__device__ float g_s[ROWS_];   // squeezed means  s[b*C + c]
__device__ float g_g[ROWS_];   // gates           g[b*C + c]

// ---------------------------------------------------------------------------
// Kernel 1: global average pool per (b,c) row. One CTA per row.
// ---------------------------------------------------------------------------
__global__ void __launch_bounds__(256) se_pool(const float* __restrict__ x,
                                               float* __restrict__ s) {
    const int row = blockIdx.x;
    const float4* __restrict__ xr =
        reinterpret_cast<const float4*>(x + (size_t)row * HW_);

    float acc = 0.0f;
    #pragma unroll 4
    for (int i = threadIdx.x; i < HW4_; i += 256) {
        float4 v = xr[i];
        acc += (v.x + v.y) + (v.z + v.w);
    }
    // warp reduce
    #pragma unroll
    for (int o = 16; o > 0; o >>= 1)
        acc += __shfl_xor_sync(0xFFFFFFFFu, acc, o);

    __shared__ float sm[8];
    if ((threadIdx.x & 31) == 0) sm[threadIdx.x >> 5] = acc;
    __syncthreads();
    if (threadIdx.x < 8) {
        float v = sm[threadIdx.x];
        #pragma unroll
        for (int o = 4; o > 0; o >>= 1)
            v += __shfl_xor_sync(0xFFu, v, o);
        if (threadIdx.x == 0) s[row] = v * (1.0f / (float)HW_);
    }
}

// ---------------------------------------------------------------------------
// Kernel 2: excitation. h = relu(s @ w1^T + b1); g = sigmoid(h @ w2^T + b2).
// Single CTA, 1024 threads. All operands tiny (fit in L2 trivially).
// ---------------------------------------------------------------------------
__global__ void __launch_bounds__(1024) se_excite(const float* __restrict__ s,
                                                  const float* __restrict__ w1,
                                                  const float* __restrict__ b1,
                                                  const float* __restrict__ w2,
                                                  const float* __restrict__ b2,
                                                  float* __restrict__ g) {
    __shared__ float h_sm[B_ * MID_];   // 32*32 = 4 KB
    const int tid = threadIdx.x;

    // h[b][m]: 1024 threads == 32*32 outputs, dot length 512
    {
        const int b = tid >> 5;          // /32
        const int m = tid & 31;
        const float* __restrict__ srow = s  + b * C_;
        const float* __restrict__ wrow = w1 + m * C_;
        float acc = b1[m];
        #pragma unroll 8
        for (int c = 0; c < C_; ++c)
            acc = fmaf(srow[c], wrow[c], acc);
        h_sm[b * MID_ + m] = fmaxf(acc, 0.0f);
    }
    __syncthreads();

    // g[b][c]: 16384 outputs / 1024 threads = 16 each, dot length 32
    for (int idx = tid; idx < B_ * C_; idx += 1024) {
        const int b = idx >> 9;          // /512
        const int c = idx & (C_ - 1);
        const float* __restrict__ wrow = w2 + c * MID_;
        const float* __restrict__ hrow = h_sm + b * MID_;
        float acc = b2[c];
        #pragma unroll
        for (int m = 0; m < MID_; ++m)
            acc = fmaf(hrow[m], wrow[m], acc);
        g[idx] = 1.0f / (1.0f + __expf(-acc));
    }
}

// ---------------------------------------------------------------------------
// Kernel 3: scale. out[b,c,:,:] = x[b,c,:,:] * g[b,c]. One CTA per row.
// ---------------------------------------------------------------------------
__global__ void __launch_bounds__(256) se_scale(const float* __restrict__ x,
                                                const float* __restrict__ g,
                                                float* __restrict__ out) {
    const int row = blockIdx.x;
    const float gv = g[row];
    const float4* __restrict__ xr =
        reinterpret_cast<const float4*>(x + (size_t)row * HW_);
    float4* __restrict__ orow =
        reinterpret_cast<float4*>(out + (size_t)row * HW_);

    #pragma unroll 4
    for (int i = threadIdx.x; i < HW4_; i += 256) {
        float4 v = xr[i];
        v.x *= gv; v.y *= gv; v.z *= gv; v.w *= gv;
        orow[i] = v;
    }
}

// ---------------------------------------------------------------------------
// Launch. Inputs (metadata order): x, w1, b1, w2, b2. Output: float32.
// ---------------------------------------------------------------------------
extern "C" void kernel_launch(void* const* d_in, const int* in_sizes, int n_in,
                              void* d_out, int out_size) {
    const float* x  = (const float*)d_in[0];
    const float* w1 = (const float*)d_in[1];
    const float* b1 = (const float*)d_in[2];
    const float* w2 = (const float*)d_in[3];
    const float* b2 = (const float*)d_in[4];
    float* out = (float*)d_out;

    float* s; cudaGetSymbolAddress((void**)&s, g_s);
    float* g; cudaGetSymbolAddress((void**)&g, g_g);

    se_pool<<<ROWS_, 256>>>(x, s);
    se_excite<<<1, 1024>>>(s, w1, b1, w2, b2, g);
    se_scale<<<ROWS_, 256>>>(x, g, out);
}

// round 9
// speedup vs baseline: 2.8807x; 2.8807x over previous
#include <cuda_runtime.h>
#include <math.h>

// Problem shape (fixed by the reference)
#define B_   32
#define C_   512
#define MID_ 32
#define HW_  3136          // 56*56
#define HW4_ 784           // HW_/4
#define ROWS_ (B_ * C_)    // 16384

// Scratch (allocation-free rule: __device__ globals)
__device__ float g_s[ROWS_];   // squeezed means  s[b*C + c]
__device__ float g_g[ROWS_];   // gates           g[b*C + c]

// ---------------------------------------------------------------------------
// Kernel 1: global average pool per (b,c) row. One CTA per row.
// Measured R1: 42.5us @ 4.9TB/s — near DRAM ceiling, unchanged.
// ---------------------------------------------------------------------------
__global__ void __launch_bounds__(256) se_pool(const float* __restrict__ x,
                                               float* __restrict__ s) {
    const int row = blockIdx.x;
    const float4* __restrict__ xr =
        reinterpret_cast<const float4*>(x + (size_t)row * HW_);

    float acc = 0.0f;
    #pragma unroll 4
    for (int i = threadIdx.x; i < HW4_; i += 256) {
        float4 v = xr[i];
        acc += (v.x + v.y) + (v.z + v.w);
    }
    // warp reduce
    #pragma unroll
    for (int o = 16; o > 0; o >>= 1)
        acc += __shfl_xor_sync(0xFFFFFFFFu, acc, o);

    __shared__ float sm[8];
    if ((threadIdx.x & 31) == 0) sm[threadIdx.x >> 5] = acc;
    __syncthreads();
    if (threadIdx.x < 8) {
        float v = sm[threadIdx.x];
        #pragma unroll
        for (int o = 4; o > 0; o >>= 1)
            v += __shfl_xor_sync(0xFFu, v, o);
        if (threadIdx.x == 0) s[row] = v * (1.0f / (float)HW_);
    }
}

// ---------------------------------------------------------------------------
// Kernel 2: excitation, coalesced rewrite (fixes the R1 L1tex-wavefront bug:
// old version had lane-strided weight reads = 32 wavefronts per LDG).
//   Pass 1: h[b][m] = relu(dot(s[b,:], w1[m,:]) + b1[m])
//           warp w owns b=w; loops m; lane strides over c
//           -> s and w1 reads fully coalesced (128B/warp), shfl reduce.
//   Pass 2: g[b][c] = sigmoid(dot(h[b,:], w2[c,:]) + b2[c])
//           thread owns one c; preloads w2 row into regs via float4 (one-time),
//           h from smem broadcast; g stores coalesced.
// ---------------------------------------------------------------------------
__global__ void __launch_bounds__(1024) se_excite(const float* __restrict__ s,
                                                  const float* __restrict__ w1,
                                                  const float* __restrict__ b1,
                                                  const float* __restrict__ w2,
                                                  const float* __restrict__ b2,
                                                  float* __restrict__ g) {
    __shared__ float h_sm[B_ * MID_];   // 32*32 = 4 KB
    const int tid  = threadIdx.x;
    const int warp = tid >> 5;
    const int lane = tid & 31;

    // ---- Pass 1: warp 'warp' handles b = warp, loops m = 0..31 ----
    {
        const int b = warp;
        const float* __restrict__ srow = s + b * C_;
        #pragma unroll 4
        for (int m = 0; m < MID_; ++m) {
            const float* __restrict__ wrow = w1 + m * C_;
            float acc = 0.0f;
            #pragma unroll
            for (int k = 0; k < C_ / 32; ++k) {
                const int c = lane + 32 * k;
                acc = fmaf(srow[c], wrow[c], acc);   // coalesced across lanes
            }
            #pragma unroll
            for (int o = 16; o > 0; o >>= 1)
                acc += __shfl_xor_sync(0xFFFFFFFFu, acc, o);
            if (lane == 0)
                h_sm[b * MID_ + m] = fmaxf(acc + b1[m], 0.0f);
        }
    }
    __syncthreads();

    // ---- Pass 2: thread owns c = tid & 511; half = tid >> 9 picks 16 b's ----
    {
        const int c    = tid & (C_ - 1);
        const int half = tid >> 9;              // 0 or 1
        const float4* __restrict__ w2r =
            reinterpret_cast<const float4*>(w2 + c * MID_);
        float4 wr[MID_ / 4];
        #pragma unroll
        for (int i = 0; i < MID_ / 4; ++i) wr[i] = w2r[i];
        const float bias = b2[c];

        const int b0 = half * (B_ / 2);
        #pragma unroll 4
        for (int b = b0; b < b0 + B_ / 2; ++b) {
            const float* __restrict__ hrow = h_sm + b * MID_;  // smem broadcast
            float acc = bias;
            #pragma unroll
            for (int i = 0; i < MID_ / 4; ++i) {
                acc = fmaf(wr[i].x, hrow[4 * i + 0], acc);
                acc = fmaf(wr[i].y, hrow[4 * i + 1], acc);
                acc = fmaf(wr[i].z, hrow[4 * i + 2], acc);
                acc = fmaf(wr[i].w, hrow[4 * i + 3], acc);
            }
            g[b * C_ + c] = 1.0f / (1.0f + __expf(-acc));      // coalesced
        }
    }
}

// ---------------------------------------------------------------------------
// Kernel 3: scale. out[b,c,:,:] = x[b,c,:,:] * g[b,c]. One CTA per row.
// Rows processed in REVERSE order: pool read rows ascending, so L2 (~126MB)
// holds the high-row tail of x — descending order maximizes L2 read hits.
// Loads use .cs (dead after read); stores use .cs (evict-first) so the
// output stream doesn't flush resident x lines.
// ---------------------------------------------------------------------------
__global__ void __launch_bounds__(256) se_scale(const float* __restrict__ x,
                                                const float* __restrict__ g,
                                                float* __restrict__ out) {
    const int row = (ROWS_ - 1) - blockIdx.x;
    const float gv = g[row];
    const float4* __restrict__ xr =
        reinterpret_cast<const float4*>(x + (size_t)row * HW_);
    float4* __restrict__ orow =
        reinterpret_cast<float4*>(out + (size_t)row * HW_);

    #pragma unroll 4
    for (int i = threadIdx.x; i < HW4_; i += 256) {
        float4 v = __ldcs(&xr[i]);
        v.x *= gv; v.y *= gv; v.z *= gv; v.w *= gv;
        __stcs(&orow[i], v);
    }
}

// ---------------------------------------------------------------------------
// Launch. Inputs (metadata order): x, w1, b1, w2, b2. Output: float32.
// ---------------------------------------------------------------------------
extern "C" void kernel_launch(void* const* d_in, const int* in_sizes, int n_in,
                              void* d_out, int out_size) {
    const float* x  = (const float*)d_in[0];
    const float* w1 = (const float*)d_in[1];
    const float* b1 = (const float*)d_in[2];
    const float* w2 = (const float*)d_in[3];
    const float* b2 = (const float*)d_in[4];
    float* out = (float*)d_out;

    float* s; cudaGetSymbolAddress((void**)&s, g_s);
    float* g; cudaGetSymbolAddress((void**)&g, g_g);

    se_pool<<<ROWS_, 256>>>(x, s);
    se_excite<<<1, 1024>>>(s, w1, b1, w2, b2, g);
    se_scale<<<ROWS_, 256>>>(x, g, out);
}